// round 5
// baseline (speedup 1.0000x reference)
#include <cuda_runtime.h>
#include <math.h>

#define B_ 8
#define N_ 4096
#define C_ 256
#define K_ 32
#define M_ (B_*N_)

// Scratch (no allocations allowed in kernel_launch)
__device__ __align__(16) float g_feat[M_*C_];
__device__ __align__(16) float g_pos[M_*C_];

// ---------------------------------------------------------------------------
// Kernel 1: feat_pos = x @ W^T + bias ; split into g_feat / g_pos
// grid = (512/64, M/64), block = 256, 64x64 tile, 4x4 micro-tile, KT=16
// ---------------------------------------------------------------------------
__global__ __launch_bounds__(256) void gemm_feat_pos(
    const float* __restrict__ x, const float* __restrict__ W,
    const float* __restrict__ bias)
{
    __shared__ float as[16][64];   // [c][row]
    __shared__ float bs[16][64];   // [c][d]
    const int tid = threadIdx.x;
    const int row0 = blockIdx.y * 64;
    const int d0   = blockIdx.x * 64;
    const int tx = tid & 15, ty = tid >> 4;
    const int lr = tid >> 2, lc = tid & 3;
    float acc[4][4] = {};
    for (int kt = 0; kt < C_; kt += 16) {
        float4 va = *(const float4*)&x[(row0 + lr) * C_ + kt + lc * 4];
        float4 vb = *(const float4*)&W[(d0 + lr) * C_ + kt + lc * 4];
        as[lc*4+0][lr]=va.x; as[lc*4+1][lr]=va.y; as[lc*4+2][lr]=va.z; as[lc*4+3][lr]=va.w;
        bs[lc*4+0][lr]=vb.x; bs[lc*4+1][lr]=vb.y; bs[lc*4+2][lr]=vb.z; bs[lc*4+3][lr]=vb.w;
        __syncthreads();
        #pragma unroll
        for (int kk = 0; kk < 16; kk++) {
            float4 a = *(const float4*)&as[kk][ty*4];
            float4 b = *(const float4*)&bs[kk][tx*4];
            float ar[4]={a.x,a.y,a.z,a.w}, br[4]={b.x,b.y,b.z,b.w};
            #pragma unroll
            for (int i=0;i<4;i++)
                #pragma unroll
                for (int j=0;j<4;j++) acc[i][j] += ar[i]*br[j];
        }
        __syncthreads();
    }
    #pragma unroll
    for (int i=0;i<4;i++) {
        int row = row0 + ty*4 + i;
        #pragma unroll
        for (int j=0;j<4;j++) {
            int d = d0 + tx*4 + j;
            float v = acc[i][j] + bias[d];
            if (d < C_) g_feat[row*C_ + d] = v;
            else        g_pos[row*C_ + d - C_] = v;
        }
    }
}

// ---------------------------------------------------------------------------
// Kernel 2: normalize pos rows. grid = M, block = 64
// ---------------------------------------------------------------------------
__global__ __launch_bounds__(64) void norm_pos()
{
    const int row = blockIdx.x;
    float* p = g_pos + row * C_;
    const int t = threadIdx.x;
    float4 v = *(float4*)&p[t*4];
    float ss = v.x*v.x + v.y*v.y + v.z*v.z + v.w*v.w;
    #pragma unroll
    for (int o = 16; o; o >>= 1) ss += __shfl_xor_sync(0xFFFFFFFFu, ss, o);
    __shared__ float s2[2];
    if ((t & 31) == 0) s2[t >> 5] = ss;
    __syncthreads();
    float tot = s2[0] + s2[1];
    float inv = 1.0f / fmaxf(sqrtf(tot), 1e-12f);
    v.x*=inv; v.y*=inv; v.z*=inv; v.w*=inv;
    *(float4*)&p[t*4] = v;
}

// ---------------------------------------------------------------------------
// Kernel 3: fused sim GEMM + streaming top-32 + softmax + gather
// grid = (N/64, B), block = 256, dynamic smem ~100 KB
// smem float layout:
//   qs:  [256][64]  q-tile transposed (c-major)   off 0      len 16384
//   ks:  [16][64]   key chunk                     off 16384  len 1024
//   st:  [64][65]   S tile (padded, scalar store) off 17408  len 4160
//   tv:  [32][64]   top values (transposed)       off 21568  len 2048
//   ti:  [32][64]   top indices (transposed)      off 23616  len 2048
// ---------------------------------------------------------------------------
#define SMEM_FLOATS 25664

__global__ __launch_bounds__(256) void topk_attn(float* __restrict__ out)
{
    extern __shared__ float sm[];
    float* qs = sm;
    float* ks = sm + 16384;
    float* st = sm + 17408;
    float* tv = sm + 21568;
    int*   ti = (int*)(sm + 23616);

    const int tid = threadIdx.x;
    const int batch = blockIdx.y;
    const int q0 = blockIdx.x * 64;
    const float* posb = g_pos + (size_t)batch * N_ * C_;

    // load 64x256 q tile, transposed to c-major
    #pragma unroll
    for (int it = 0; it < 16; it++) {
        int f4 = it * 256 + tid;
        int r = f4 >> 6, c4 = f4 & 63;
        float4 v = *(const float4*)&posb[(q0 + r) * C_ + c4 * 4];
        qs[(c4*4+0)*64+r]=v.x; qs[(c4*4+1)*64+r]=v.y;
        qs[(c4*4+2)*64+r]=v.z; qs[(c4*4+3)*64+r]=v.w;
    }

    // per-row top-k state (thread tid<64 owns row tid for the whole kernel)
    int cnt = 0, thrp = 0;
    float thrv = 3.0e38f;

    const int tx = tid & 15, ty = tid >> 4;
    const int lr = tid >> 2, lc = tid & 3;
    __syncthreads();

    for (int kt0 = 0; kt0 < N_; kt0 += 64) {
        float acc[4][4] = {};
        for (int c0 = 0; c0 < C_; c0 += 16) {
            float4 v = *(const float4*)&posb[(kt0 + lr) * C_ + c0 + lc*4];
            ks[(lc*4+0)*64+lr]=v.x; ks[(lc*4+1)*64+lr]=v.y;
            ks[(lc*4+2)*64+lr]=v.z; ks[(lc*4+3)*64+lr]=v.w;
            __syncthreads();
            #pragma unroll
            for (int kk = 0; kk < 16; kk++) {
                float4 a = *(const float4*)&qs[(c0+kk)*64 + ty*4];
                float4 b = *(const float4*)&ks[kk*64 + tx*4];
                float ar[4]={a.x,a.y,a.z,a.w}, br[4]={b.x,b.y,b.z,b.w};
                #pragma unroll
                for (int i=0;i<4;i++)
                    #pragma unroll
                    for (int j=0;j<4;j++) acc[i][j] += ar[i]*br[j];
            }
            __syncthreads();
        }
        // dump S tile (SCALAR stores — stride 65 is not float4-alignable)
        #pragma unroll
        for (int i=0;i<4;i++)
            #pragma unroll
            for (int j=0;j<4;j++)
                st[(ty*4+i)*65 + tx*4 + j] = acc[i][j];
        __syncthreads();
        // streaming top-32 per row (threshold filter + argmin replace)
        if (tid < 64) {
            const int r = tid;
            for (int j = 0; j < 64; j++) {
                float v = st[r*65 + j];
                if (cnt < K_) {
                    tv[cnt*64 + r] = v; ti[cnt*64 + r] = kt0 + j;
                    if (v < thrv) { thrv = v; thrp = cnt; }
                    cnt++;
                } else if (v > thrv) {
                    tv[thrp*64 + r] = v; ti[thrp*64 + r] = kt0 + j;
                    thrv = tv[r]; thrp = 0;
                    #pragma unroll
                    for (int i = 1; i < K_; i++) {
                        float t2 = tv[i*64 + r];
                        if (t2 < thrv) { thrv = t2; thrp = i; }
                    }
                }
            }
        }
        __syncthreads();
    }

    // softmax per row over the 32 kept values (order-invariant)
    if (tid < 64) {
        const int r = tid;
        float m = -3.0e38f;
        #pragma unroll
        for (int i=0;i<K_;i++) m = fmaxf(m, tv[i*64+r]);
        float s = 0.f;
        #pragma unroll
        for (int i=0;i<K_;i++) { float e = expf(tv[i*64+r]-m); tv[i*64+r]=e; s+=e; }
        float inv = 1.0f/s;
        #pragma unroll
        for (int i=0;i<K_;i++) tv[i*64+r] *= inv;
    }
    __syncthreads();

    // gather: out[row] = sum_i w_i * feat[idx_i]; one warp per row, 8 cols/lane
    const int warp = tid >> 5, lane = tid & 31;
    const float* fb = g_feat + (size_t)batch * N_ * C_;
    for (int rr = warp; rr < 64; rr += 8) {
        float a0[4]={0.f,0.f,0.f,0.f}, a1[4]={0.f,0.f,0.f,0.f};
        #pragma unroll 4
        for (int i = 0; i < K_; i++) {
            float w = tv[i*64+rr];
            const float* f = fb + (size_t)ti[i*64+rr]*C_ + lane*8;
            float4 u  = *(const float4*)f;
            float4 u2 = *(const float4*)(f+4);
            a0[0]+=w*u.x;  a0[1]+=w*u.y;  a0[2]+=w*u.z;  a0[3]+=w*u.w;
            a1[0]+=w*u2.x; a1[1]+=w*u2.y; a1[2]+=w*u2.z; a1[3]+=w*u2.w;
        }
        float* o = out + ((size_t)batch*N_ + q0 + rr)*C_ + lane*8;
        *(float4*)o     = make_float4(a0[0],a0[1],a0[2],a0[3]);
        *(float4*)(o+4) = make_float4(a1[0],a1[1],a1[2],a1[3]);
    }
}

// ---------------------------------------------------------------------------
extern "C" void kernel_launch(void* const* d_in, const int* in_sizes, int n_in,
                              void* d_out, int out_size)
{
    const float* x    = (const float*)d_in[0];
    const float* W    = (const float*)d_in[1];
    const float* bias = (const float*)d_in[2];
    float* out = (float*)d_out;

    gemm_feat_pos<<<dim3(512/64, M_/64), 256>>>(x, W, bias);
    norm_pos<<<M_, 64>>>();

    const int smem_bytes = SMEM_FLOATS * (int)sizeof(float);
    cudaFuncSetAttribute(topk_attn, cudaFuncAttributeMaxDynamicSharedMemorySize,
                         smem_bytes);
    topk_attn<<<dim3(N_/64, B_), 256, smem_bytes>>>(out);
}